// round 1
// baseline (speedup 1.0000x reference)
#include <cuda_runtime.h>
#include <cuda_bf16.h>

// Fused quanvolution + linear + log_softmax.
// One block = one sample. 256 threads: threads 0..195 each own one 2x2 patch.
//
// Per patch p (r=p/14, c=p%14):
//   theta = [x(2r,2c), x(2r,2c+1), x(2r+1,2c), x(2r+1,2c+1)] * 0.5
//   a_q = (cos th_q, sin th_q);  s = a0 (x) a1 (x) a2 (x) a3   (16)
//   t = U s;  p_e = t_e^2;  meas_q = sum_e sign_q(e) p_e  (Walsh butterfly)
// feat[p*4+q] -> shared; logits = feat @ W^T + b; log_softmax.

#define NTHR 256

__global__ __launch_bounds__(NTHR) void quanv_fused_kernel(
    const float* __restrict__ x,   // (B, 784)
    const float* __restrict__ U,   // (16, 16) row-major
    const float* __restrict__ W,   // (10, 784) row-major
    const float* __restrict__ bias,// (10)
    float* __restrict__ out)       // (B, 10)
{
    __shared__ float img[784];
    __shared__ float Us[256];
    __shared__ float feat[784];
    __shared__ float red[8 * 10];
    __shared__ float lg[10];

    const int tid = threadIdx.x;
    const int sample = blockIdx.x;

    // Stage image + U into shared (coalesced float4)
    {
        const float4* x4 = (const float4*)(x + (size_t)sample * 784);
        if (tid < 196) ((float4*)img)[tid] = x4[tid];
        if (tid < 64)  ((float4*)Us)[tid]  = ((const float4*)U)[tid];
    }
    __syncthreads();

    if (tid < 196) {
        const int r = tid / 14;
        const int c = tid - r * 14;
        const float2* img2 = (const float2*)img;
        // row 2r cols (2c,2c+1) ; row 2r+1 cols (2c,2c+1)
        float2 top = img2[r * 28 + c];
        float2 bot = img2[r * 28 + 14 + c];

        float s0, c0, s1, c1, s2, c2, s3, c3;
        __sincosf(0.5f * top.x, &s0, &c0);
        __sincosf(0.5f * top.y, &s1, &c1);
        __sincosf(0.5f * bot.x, &s2, &c2);
        __sincosf(0.5f * bot.y, &s3, &c3);

        // product state, index = i*8 + j*4 + k*2 + l (i = wire 0 = MSB)
        float v01[4] = { c0 * c1, c0 * s1, s0 * c1, s0 * s1 };
        float v23[4] = { c2 * c3, c2 * s3, s2 * c3, s2 * s3 };
        float sv[16];
        #pragma unroll
        for (int m = 0; m < 4; m++)
            #pragma unroll
            for (int n = 0; n < 4; n++)
                sv[m * 4 + n] = v01[m] * v23[n];

        // t = U s ; p = t*t.  U rows read as broadcast LDS.128 (conflict-free).
        float p[16];
        const float4* U4 = (const float4*)Us;
        #pragma unroll
        for (int e = 0; e < 16; e++) {
            float4 u0 = U4[e * 4 + 0];
            float4 u1 = U4[e * 4 + 1];
            float4 u2 = U4[e * 4 + 2];
            float4 u3 = U4[e * 4 + 3];
            float t = u0.x * sv[0];
            t = fmaf(u0.y, sv[1], t);  t = fmaf(u0.z, sv[2],  t);  t = fmaf(u0.w, sv[3],  t);
            t = fmaf(u1.x, sv[4], t);  t = fmaf(u1.y, sv[5],  t);  t = fmaf(u1.z, sv[6],  t);
            t = fmaf(u1.w, sv[7], t);  t = fmaf(u2.x, sv[8],  t);  t = fmaf(u2.y, sv[9],  t);
            t = fmaf(u2.z, sv[10], t); t = fmaf(u2.w, sv[11], t);  t = fmaf(u3.x, sv[12], t);
            t = fmaf(u3.y, sv[13], t); t = fmaf(u3.z, sv[14], t);  t = fmaf(u3.w, sv[15], t);
            p[e] = t * t;
        }

        // Walsh butterfly: meas_q = sum_e (1 - 2*bit_{3-q}(e)) * p[e]
        float m3 = 0.f, m2 = 0.f, m1 = 0.f, m0;
        float g8[8];
        #pragma unroll
        for (int i = 0; i < 8; i++) {
            g8[i] = p[2 * i] + p[2 * i + 1];
            m3   += p[2 * i] - p[2 * i + 1];
        }
        float g4[4];
        #pragma unroll
        for (int i = 0; i < 4; i++) {
            g4[i] = g8[2 * i] + g8[2 * i + 1];
            m2   += g8[2 * i] - g8[2 * i + 1];
        }
        float g2[2];
        #pragma unroll
        for (int i = 0; i < 2; i++) {
            g2[i] = g4[2 * i] + g4[2 * i + 1];
            m1   += g4[2 * i] - g4[2 * i + 1];
        }
        m0 = g2[0] - g2[1];

        feat[tid * 4 + 0] = m0;
        feat[tid * 4 + 1] = m1;
        feat[tid * 4 + 2] = m2;
        feat[tid * 4 + 3] = m3;
    }
    __syncthreads();

    // Linear: logits[c] = sum_j feat[j] * W[c][j] + b[c]
    float partial[10];
    #pragma unroll
    for (int c = 0; c < 10; c++) partial[c] = 0.f;

    if (tid < 196) {
        float4 f4 = ((const float4*)feat)[tid];
        #pragma unroll
        for (int c = 0; c < 10; c++) {
            float4 w4 = ((const float4*)(W + c * 784))[tid];
            float acc = f4.x * w4.x;
            acc = fmaf(f4.y, w4.y, acc);
            acc = fmaf(f4.z, w4.z, acc);
            acc = fmaf(f4.w, w4.w, acc);
            partial[c] = acc;
        }
    }

    // Warp reduce then cross-warp reduce in shared
    #pragma unroll
    for (int c = 0; c < 10; c++) {
        #pragma unroll
        for (int o = 16; o > 0; o >>= 1)
            partial[c] += __shfl_xor_sync(0xffffffffu, partial[c], o);
    }
    const int warp = tid >> 5;
    const int lane = tid & 31;
    if (lane == 0) {
        #pragma unroll
        for (int c = 0; c < 10; c++) red[warp * 10 + c] = partial[c];
    }
    __syncthreads();

    if (tid < 10) {
        float v = bias[tid];
        #pragma unroll
        for (int w = 0; w < 8; w++) v += red[w * 10 + tid];
        lg[tid] = v;
    }
    __syncthreads();

    if (tid < 10) {
        float mx = lg[0];
        #pragma unroll
        for (int i = 1; i < 10; i++) mx = fmaxf(mx, lg[i]);
        float s = 0.f;
        #pragma unroll
        for (int i = 0; i < 10; i++) s += __expf(lg[i] - mx);
        out[(size_t)sample * 10 + tid] = lg[tid] - mx - __logf(s);
    }
}

extern "C" void kernel_launch(void* const* d_in, const int* in_sizes, int n_in,
                              void* d_out, int out_size) {
    const float* x  = (const float*)d_in[0];
    const float* U  = (const float*)d_in[1];
    const float* W  = (const float*)d_in[2];
    const float* b  = (const float*)d_in[3];
    float* out = (float*)d_out;
    int B = in_sizes[0] / 784;
    quanv_fused_kernel<<<B, NTHR>>>(x, U, W, b, out);
}

// round 2
// speedup vs baseline: 1.1657x; 1.1657x over previous
#include <cuda_runtime.h>
#include <cuda_bf16.h>

// Fused quanvolution + linear + log_softmax.
// One block = one sample. 256 threads: threads 0..195 each own one 2x2 patch.
// U (16x16) lives in __constant__ memory -> warp-uniform LDCU + UR-operand FFMA,
// keeping the L1/shared pipe free for the W loads in the linear layer.

#define NTHR 256

__constant__ float Uc[256];

__global__ __launch_bounds__(NTHR) void quanv_fused_kernel(
    const float* __restrict__ x,   // (B, 784)
    const float* __restrict__ W,   // (10, 784) row-major
    const float* __restrict__ bias,// (10)
    float* __restrict__ out)       // (B, 10)
{
    __shared__ float feat[784];
    __shared__ float red[8 * 10];
    __shared__ float lg[10];

    const int tid = threadIdx.x;
    const int sample = blockIdx.x;
    const float* xs = x + (size_t)sample * 784;

    if (tid < 196) {
        const int r = tid / 14;
        const int c = tid - r * 14;
        // pixels: x[2r][2c], x[2r][2c+1], x[2r+1][2c], x[2r+1][2c+1]
        const float2* row0 = (const float2*)(xs + (2 * r) * 28);
        const float2* row1 = (const float2*)(xs + (2 * r + 1) * 28);
        float2 top = row0[c];
        float2 bot = row1[c];

        float s0, c0, s1, c1, s2, c2, s3, c3;
        __sincosf(0.5f * top.x, &s0, &c0);
        __sincosf(0.5f * top.y, &s1, &c1);
        __sincosf(0.5f * bot.x, &s2, &c2);
        __sincosf(0.5f * bot.y, &s3, &c3);

        // product state, index = i*8 + j*4 + k*2 + l (wire 0 = MSB)
        float v01[4] = { c0 * c1, c0 * s1, s0 * c1, s0 * s1 };
        float v23[4] = { c2 * c3, c2 * s3, s2 * c3, s2 * s3 };
        float sv[16];
        #pragma unroll
        for (int m = 0; m < 4; m++)
            #pragma unroll
            for (int n = 0; n < 4; n++)
                sv[m * 4 + n] = v01[m] * v23[n];

        // t = U s ; p = t*t.  U from __constant__: uniform LDCU, no L1 traffic.
        float p[16];
        #pragma unroll
        for (int e = 0; e < 16; e++) {
            float t = Uc[e * 16] * sv[0];
            #pragma unroll
            for (int f = 1; f < 16; f++)
                t = fmaf(Uc[e * 16 + f], sv[f], t);
            p[e] = t * t;
        }

        // Walsh butterfly: meas_q = sum_e (1 - 2*bit_{3-q}(e)) * p[e]
        float m3 = 0.f, m2 = 0.f, m1 = 0.f, m0;
        float g8[8];
        #pragma unroll
        for (int i = 0; i < 8; i++) {
            g8[i] = p[2 * i] + p[2 * i + 1];
            m3   += p[2 * i] - p[2 * i + 1];
        }
        float g4[4];
        #pragma unroll
        for (int i = 0; i < 4; i++) {
            g4[i] = g8[2 * i] + g8[2 * i + 1];
            m2   += g8[2 * i] - g8[2 * i + 1];
        }
        float g2[2];
        #pragma unroll
        for (int i = 0; i < 2; i++) {
            g2[i] = g4[2 * i] + g4[2 * i + 1];
            m1   += g4[2 * i] - g4[2 * i + 1];
        }
        m0 = g2[0] - g2[1];

        feat[tid * 4 + 0] = m0;
        feat[tid * 4 + 1] = m1;
        feat[tid * 4 + 2] = m2;
        feat[tid * 4 + 3] = m3;
    }
    __syncthreads();

    // Linear: logits[c] = sum_j feat[j] * W[c][j] + b[c]
    float partial[10];
    #pragma unroll
    for (int c = 0; c < 10; c++) partial[c] = 0.f;

    if (tid < 196) {
        float4 f4 = ((const float4*)feat)[tid];
        #pragma unroll
        for (int c = 0; c < 10; c++) {
            float4 w4 = ((const float4*)(W + c * 784))[tid];
            float acc = f4.x * w4.x;
            acc = fmaf(f4.y, w4.y, acc);
            acc = fmaf(f4.z, w4.z, acc);
            acc = fmaf(f4.w, w4.w, acc);
            partial[c] = acc;
        }
    }

    // Warp reduce then cross-warp reduce in shared
    #pragma unroll
    for (int c = 0; c < 10; c++) {
        #pragma unroll
        for (int o = 16; o > 0; o >>= 1)
            partial[c] += __shfl_xor_sync(0xffffffffu, partial[c], o);
    }
    const int warp = tid >> 5;
    const int lane = tid & 31;
    if (lane == 0) {
        #pragma unroll
        for (int c = 0; c < 10; c++) red[warp * 10 + c] = partial[c];
    }
    __syncthreads();

    if (tid < 10) {
        float v = bias[tid];
        #pragma unroll
        for (int w = 0; w < 8; w++) v += red[w * 10 + tid];
        lg[tid] = v;
    }
    __syncthreads();

    if (tid < 10) {
        float mx = lg[0];
        #pragma unroll
        for (int i = 1; i < 10; i++) mx = fmaxf(mx, lg[i]);
        float s = 0.f;
        #pragma unroll
        for (int i = 0; i < 10; i++) s += __expf(lg[i] - mx);
        out[(size_t)sample * 10 + tid] = lg[tid] - mx - __logf(s);
    }
}

extern "C" void kernel_launch(void* const* d_in, const int* in_sizes, int n_in,
                              void* d_out, int out_size) {
    const float* x  = (const float*)d_in[0];
    const float* U  = (const float*)d_in[1];
    const float* W  = (const float*)d_in[2];
    const float* b  = (const float*)d_in[3];
    float* out = (float*)d_out;
    int B = in_sizes[0] / 784;
    cudaMemcpyToSymbolAsync(Uc, U, 256 * sizeof(float), 0,
                            cudaMemcpyDeviceToDevice);
    quanv_fused_kernel<<<B, NTHR>>>(x, W, b, out);
}